// round 8
// baseline (speedup 1.0000x reference)
#include <cuda_runtime.h>

// Embedder: multirate zero-insert upsample -> conv1d(1->256, K=5, same) -> gather.
// Closed-form FIR taps. Output = X[3,256,60000] ++ S[2,60000] (~185 MB).
//
// R8 = R5 layout (256-thr blocks, 1 float4/thread, grid 1534, high occ)
//    + R7 math (fma.rn.f32x2, input pairs hoisted out of d-loop, weights
//      pre-duplicated (w,w) in smem, LDS.128 weight fetch).

#define L250   15000
#define L500   30000
#define L1000  60000
#define ROW4   15000
#define X4TOT  (768 * ROW4)                // 11,520,000 float4
#define S4TOT  30000
#define NCH    59                          // ceil(15000/256)
#define NDG    8
#define DG     32
#define XBLOCKS (3 * NCH * NDG)            // 1416
#define SBLOCKS ((S4TOT + 255) / 256)      // 118

typedef unsigned long long u64t;

__device__ __forceinline__ u64t pk(float lo, float hi) {
    u64t r; asm("mov.b64 %0, {%1, %2};" : "=l"(r) : "f"(lo), "f"(hi)); return r;
}
__device__ __forceinline__ u64t f2(u64t a, u64t b, u64t c) {
    u64t d; asm("fma.rn.f32x2 %0, %1, %2, %3;" : "=l"(d) : "l"(a), "l"(b), "l"(c)); return d;
}
union Cvt { ulonglong2 u; float4 f; };

__device__ __forceinline__ float ldx(const float* __restrict__ x, int i, int l) {
    return (i >= 0 && i < l) ? __ldg(x + i) : 0.0f;
}

__global__ void __launch_bounds__(256)
embedder_kernel(const float* __restrict__ x250,
                const float* __restrict__ x500,
                const float* __restrict__ x1000,
                const float* __restrict__ W,   // [256,1,5]
                const float* __restrict__ b,   // [256]
                float4* __restrict__ out)
{
    int blk = blockIdx.x;

    if (blk < XBLOCKS) {
        int stream = blk / (NCH * NDG);
        int rem    = blk - stream * (NCH * NDG);
        int chunk  = rem >> 3;
        int g      = rem & 7;
        int t      = threadIdx.x;

        // (w,w) pairs: row = 6 float2 = 48B, 16B-aligned -> LDS.128-able
        __shared__ float2 swp[DG][6];
        if (t < DG) {
            int d = g * DG + t;
            #pragma unroll
            for (int k = 0; k < 5; k++) { float w = __ldg(W + d * 5 + k); swp[t][k] = make_float2(w, w); }
            float bb = __ldg(b + d); swp[t][5] = make_float2(bb, bb);
        }
        __syncthreads();

        int f4 = chunk * 256 + t;
        if (f4 >= ROW4) return;
        int p = f4 * 4;

        float4* po = out + ((long)(stream * 256 + g * DG) * ROW4 + f4);
        const float4 ZZ = make_float4(0.f, 0.f, 0.f, 0.f);
        const ulonglong2* wq = (const ulonglong2*)&swp[0][0];   // 3 x 16B per d

        if (stream == 0) {
            if (f4 < 3750) {                  // p < 15000
                float4 c = __ldg((const float4*)x250 + f4);
                u64t A01 = pk(c.x, c.y), A23 = pk(c.z, c.w);
                #pragma unroll 4
                for (int i = 0; i < DG; i++) {
                    ulonglong2 q1 = wq[i * 3 + 1];   // (w2,w2),(w3,w3)
                    ulonglong2 q2 = wq[i * 3 + 2];   // (w4,w4),(b,b)
                    u64t W2 = q1.x, BB = q2.y;
                    Cvt o;
                    o.u.x = f2(W2, A01, BB);
                    o.u.y = f2(W2, A23, BB);
                    __stcs(po, o.f);  po += ROW4;
                }
            } else {
                #pragma unroll 8
                for (int i = 0; i < DG; i++) { __stcs(po, ZZ); po += ROW4; }
            }
        } else if (stream == 1) {
            if (f4 < 7500) {                  // p < 30000
                float v0 = ldx(x500, p - 1, L500);
                float4 c = __ldg((const float4*)x500 + f4);
                float v5 = ldx(x500, p + 4, L500);
                u64t Q0 = pk(v0, c.x), Q1 = pk(c.x, c.y), Q2 = pk(c.y, c.z),
                     Q3 = pk(c.z, c.w), Q4 = pk(c.w, v5);
                #pragma unroll 4
                for (int i = 0; i < DG; i++) {
                    ulonglong2 q0 = wq[i * 3 + 0];   // W0, W1
                    ulonglong2 q1 = wq[i * 3 + 1];   // W2, W3
                    ulonglong2 q2 = wq[i * 3 + 2];   // W4, BB
                    u64t W0 = q0.x, W2 = q1.x, W4 = q2.x, BB = q2.y;
                    Cvt o;
                    o.u.x = f2(W0, Q0, f2(W2, Q1, f2(W4, Q2, BB)));
                    o.u.y = f2(W0, Q2, f2(W2, Q3, f2(W4, Q4, BB)));
                    __stcs(po, o.f);  po += ROW4;
                }
            } else {
                #pragma unroll 8
                for (int i = 0; i < DG; i++) { __stcs(po, ZZ); po += ROW4; }
            }
        } else {
            float u0 = ldx(x1000, p - 2, L1000);
            float u1 = ldx(x1000, p - 1, L1000);
            float4 c = __ldg((const float4*)x1000 + f4);
            float u6 = ldx(x1000, p + 4, L1000);
            float u7 = ldx(x1000, p + 5, L1000);
            u64t P0 = pk(u0, u1),  P1 = pk(u1, c.x), P2 = pk(c.x, c.y),
                 P3 = pk(c.y, c.z), P4 = pk(c.z, c.w), P5 = pk(c.w, u6),
                 P6 = pk(u6, u7);
            #pragma unroll 4
            for (int i = 0; i < DG; i++) {
                ulonglong2 q0 = wq[i * 3 + 0];   // W0, W1
                ulonglong2 q1 = wq[i * 3 + 1];   // W2, W3
                ulonglong2 q2 = wq[i * 3 + 2];   // W4, BB
                u64t W0 = q0.x, W1 = q0.y, W2 = q1.x, W3 = q1.y, W4 = q2.x, BB = q2.y;
                Cvt o;
                o.u.x = f2(W0, P0, f2(W1, P1, f2(W2, P2, f2(W3, P3, f2(W4, P4, BB)))));
                o.u.y = f2(W0, P2, f2(W1, P3, f2(W2, P4, f2(W3, P5, f2(W4, P6, BB)))));
                __stcs(po, o.f);  po += ROW4;
            }
        }
    } else {
        // S = [rows(60000), cols(60000)] as float
        int i = (blk - XBLOCKS) * 256 + threadIdx.x;
        if (i < S4TOT) {
            int e = i * 4;
            float4 o;
            float* pf = (float*)&o;
            if (e < L1000) {
                float r = (e < L250) ? 0.f : ((e < L250 + L500) ? 1.f : 2.f);
                o = make_float4(r, r, r, r);
            } else {
                int p = e - L1000;
                #pragma unroll
                for (int k = 0; k < 4; k++) {
                    int q = p + k;
                    float cc;
                    if (q < L250)             cc = (float)(q * 4);
                    else if (q < L250 + L500) cc = (float)((q - L250) * 2);
                    else                      cc = (float)(q - (L250 + L500));
                    pf[k] = cc;
                }
            }
            __stcs(out + X4TOT + i, o);
        }
    }
}

extern "C" void kernel_launch(void* const* d_in, const int* in_sizes, int n_in,
                              void* d_out, int out_size) {
    const float* x250  = (const float*)d_in[0];
    const float* x500  = (const float*)d_in[1];
    const float* x1000 = (const float*)d_in[2];
    const float* W     = (const float*)d_in[3];
    const float* b     = (const float*)d_in[4];
    float4* out = (float4*)d_out;

    embedder_kernel<<<XBLOCKS + SBLOCKS, 256>>>(x250, x500, x1000, W, b, out);
}

// round 9
// speedup vs baseline: 1.2962x; 1.2962x over previous
#include <cuda_runtime.h>

// Embedder: multirate zero-insert upsample -> conv1d(1->256, K=5, same) -> gather.
// Closed-form FIR taps. Output = X[3,256,60000] ++ S[2,60000] (~185 MB).
//
// R9 = R5 layout (256-thr blocks, NDG=8, 1 float4/thread, occ ~59%)
//    + FFMA2 math (input pairs hoisted out of d-loop)
//    + weights fetched via explicit LDS.64 broadcasts (inline asm; R8 showed
//      uniform LDS.128 is multi-wavefront-expensive and must be avoided).

#define L250   15000
#define L500   30000
#define L1000  60000
#define ROW4   15000
#define X4TOT  (768 * ROW4)                // 11,520,000 float4
#define S4TOT  30000
#define NCH    59                          // ceil(15000/256)
#define NDG    8
#define DG     32
#define XBLOCKS (3 * NCH * NDG)            // 1416
#define SBLOCKS ((S4TOT + 255) / 256)      // 118

typedef unsigned long long u64t;

__device__ __forceinline__ u64t pk(float lo, float hi) {
    u64t r; asm("mov.b64 %0, {%1, %2};" : "=l"(r) : "f"(lo), "f"(hi)); return r;
}
__device__ __forceinline__ u64t f2(u64t a, u64t b, u64t c) {
    u64t d; asm("fma.rn.f32x2 %0, %1, %2, %3;" : "=l"(d) : "l"(a), "l"(b), "l"(c)); return d;
}
__device__ __forceinline__ u64t lds64(unsigned addr) {
    u64t r; asm("ld.shared.b64 %0, [%1];" : "=l"(r) : "r"(addr)); return r;
}
union Cvt { ulonglong2 u; float4 f; };

__device__ __forceinline__ float ldx(const float* __restrict__ x, int i, int l) {
    return (i >= 0 && i < l) ? __ldg(x + i) : 0.0f;
}

__global__ void __launch_bounds__(256)
embedder_kernel(const float* __restrict__ x250,
                const float* __restrict__ x500,
                const float* __restrict__ x1000,
                const float* __restrict__ W,   // [256,1,5]
                const float* __restrict__ b,   // [256]
                float4* __restrict__ out)
{
    int blk = blockIdx.x;

    if (blk < XBLOCKS) {
        int stream = blk / (NCH * NDG);
        int rem    = blk - stream * (NCH * NDG);
        int chunk  = rem >> 3;
        int g      = rem & 7;
        int t      = threadIdx.x;

        // duplicated (w,w) pairs, row = 6 float2 = 48B
        __shared__ float2 swp[DG][6];
        if (t < DG) {
            int d = g * DG + t;
            #pragma unroll
            for (int k = 0; k < 5; k++) { float w = __ldg(W + d * 5 + k); swp[t][k] = make_float2(w, w); }
            float bb = __ldg(b + d); swp[t][5] = make_float2(bb, bb);
        }
        __syncthreads();

        unsigned wbase;
        { unsigned long long ga = __cvta_generic_to_shared(&swp[0][0]); wbase = (unsigned)ga; }

        int f4 = chunk * 256 + t;
        if (f4 >= ROW4) return;
        int p = f4 * 4;

        float4* po = out + ((long)(stream * 256 + g * DG) * ROW4 + f4);
        const float4 ZZ = make_float4(0.f, 0.f, 0.f, 0.f);

        if (stream == 0) {
            if (f4 < 3750) {                  // p < 15000
                float4 c = __ldg((const float4*)x250 + f4);
                u64t A01 = pk(c.x, c.y), A23 = pk(c.z, c.w);
                #pragma unroll 4
                for (int i = 0; i < DG; i++) {
                    unsigned wa = wbase + i * 48;
                    u64t W2 = lds64(wa + 16);
                    u64t BB = lds64(wa + 40);
                    Cvt o;
                    o.u.x = f2(W2, A01, BB);
                    o.u.y = f2(W2, A23, BB);
                    __stcs(po, o.f);  po += ROW4;
                }
            } else {
                #pragma unroll 8
                for (int i = 0; i < DG; i++) { __stcs(po, ZZ); po += ROW4; }
            }
        } else if (stream == 1) {
            if (f4 < 7500) {                  // p < 30000
                float v0 = ldx(x500, p - 1, L500);
                float4 c = __ldg((const float4*)x500 + f4);
                float v5 = ldx(x500, p + 4, L500);
                u64t Q0 = pk(v0, c.x), Q1 = pk(c.x, c.y), Q2 = pk(c.y, c.z),
                     Q3 = pk(c.z, c.w), Q4 = pk(c.w, v5);
                #pragma unroll 4
                for (int i = 0; i < DG; i++) {
                    unsigned wa = wbase + i * 48;
                    u64t W0 = lds64(wa + 0);
                    u64t W2 = lds64(wa + 16);
                    u64t W4 = lds64(wa + 32);
                    u64t BB = lds64(wa + 40);
                    Cvt o;
                    o.u.x = f2(W0, Q0, f2(W2, Q1, f2(W4, Q2, BB)));
                    o.u.y = f2(W0, Q2, f2(W2, Q3, f2(W4, Q4, BB)));
                    __stcs(po, o.f);  po += ROW4;
                }
            } else {
                #pragma unroll 8
                for (int i = 0; i < DG; i++) { __stcs(po, ZZ); po += ROW4; }
            }
        } else {
            float u0 = ldx(x1000, p - 2, L1000);
            float u1 = ldx(x1000, p - 1, L1000);
            float4 c = __ldg((const float4*)x1000 + f4);
            float u6 = ldx(x1000, p + 4, L1000);
            float u7 = ldx(x1000, p + 5, L1000);
            u64t P0 = pk(u0, u1),  P1 = pk(u1, c.x), P2 = pk(c.x, c.y),
                 P3 = pk(c.y, c.z), P4 = pk(c.z, c.w), P5 = pk(c.w, u6),
                 P6 = pk(u6, u7);
            #pragma unroll 4
            for (int i = 0; i < DG; i++) {
                unsigned wa = wbase + i * 48;
                u64t W0 = lds64(wa + 0);
                u64t W1 = lds64(wa + 8);
                u64t W2 = lds64(wa + 16);
                u64t W3 = lds64(wa + 24);
                u64t W4 = lds64(wa + 32);
                u64t BB = lds64(wa + 40);
                Cvt o;
                o.u.x = f2(W0, P0, f2(W1, P1, f2(W2, P2, f2(W3, P3, f2(W4, P4, BB)))));
                o.u.y = f2(W0, P2, f2(W1, P3, f2(W2, P4, f2(W3, P5, f2(W4, P6, BB)))));
                __stcs(po, o.f);  po += ROW4;
            }
        }
    } else {
        // S = [rows(60000), cols(60000)] as float
        int i = (blk - XBLOCKS) * 256 + threadIdx.x;
        if (i < S4TOT) {
            int e = i * 4;
            float4 o;
            float* pf = (float*)&o;
            if (e < L1000) {
                float r = (e < L250) ? 0.f : ((e < L250 + L500) ? 1.f : 2.f);
                o = make_float4(r, r, r, r);
            } else {
                int p = e - L1000;
                #pragma unroll
                for (int k = 0; k < 4; k++) {
                    int q = p + k;
                    float cc;
                    if (q < L250)             cc = (float)(q * 4);
                    else if (q < L250 + L500) cc = (float)((q - L250) * 2);
                    else                      cc = (float)(q - (L250 + L500));
                    pf[k] = cc;
                }
            }
            __stcs(out + X4TOT + i, o);
        }
    }
}

extern "C" void kernel_launch(void* const* d_in, const int* in_sizes, int n_in,
                              void* d_out, int out_size) {
    const float* x250  = (const float*)d_in[0];
    const float* x500  = (const float*)d_in[1];
    const float* x1000 = (const float*)d_in[2];
    const float* W     = (const float*)d_in[3];
    const float* b     = (const float*)d_in[4];
    float4* out = (float4*)d_out;

    embedder_kernel<<<XBLOCKS + SBLOCKS, 256>>>(x250, x500, x1000, W, b, out);
}

// round 10
// speedup vs baseline: 1.3049x; 1.0068x over previous
#include <cuda_runtime.h>

// Embedder: multirate zero-insert upsample -> conv1d(1->256, K=5, same) -> gather.
// Closed-form FIR taps. Output = X[3,256,60000] ++ S[2,60000] (~185 MB).
//
// R10 = R9 (FFMA2 + hoisted input pairs + LDS.64 weight broadcasts)
//     - __stcs  -> plain stores: let output sit DIRTY in L2 across graph
//       replays (same addresses rewritten each replay -> no DRAM drain for
//       the L2-resident ~126MB). Tests DRAM-write-drain as the soft binder.
//     + NDG=16 (DG=16): grid 2950 for smoother tail.

#define L250   15000
#define L500   30000
#define L1000  60000
#define ROW4   15000
#define X4TOT  (768 * ROW4)                // 11,520,000 float4
#define S4TOT  30000
#define NCH    59                          // ceil(15000/256)
#define NDG    16
#define DG     16
#define XBLOCKS (3 * NCH * NDG)            // 2832
#define SBLOCKS ((S4TOT + 255) / 256)      // 118

typedef unsigned long long u64t;

__device__ __forceinline__ u64t pk(float lo, float hi) {
    u64t r; asm("mov.b64 %0, {%1, %2};" : "=l"(r) : "f"(lo), "f"(hi)); return r;
}
__device__ __forceinline__ u64t f2(u64t a, u64t b, u64t c) {
    u64t d; asm("fma.rn.f32x2 %0, %1, %2, %3;" : "=l"(d) : "l"(a), "l"(b), "l"(c)); return d;
}
__device__ __forceinline__ u64t lds64(unsigned addr) {
    u64t r; asm("ld.shared.b64 %0, [%1];" : "=l"(r) : "r"(addr)); return r;
}
union Cvt { ulonglong2 u; float4 f; };

__device__ __forceinline__ float ldx(const float* __restrict__ x, int i, int l) {
    return (i >= 0 && i < l) ? __ldg(x + i) : 0.0f;
}

__global__ void __launch_bounds__(256)
embedder_kernel(const float* __restrict__ x250,
                const float* __restrict__ x500,
                const float* __restrict__ x1000,
                const float* __restrict__ W,   // [256,1,5]
                const float* __restrict__ b,   // [256]
                float4* __restrict__ out)
{
    int blk = blockIdx.x;

    if (blk < XBLOCKS) {
        int stream = blk / (NCH * NDG);
        int rem    = blk - stream * (NCH * NDG);
        int chunk  = rem >> 4;                 // / NDG
        int g      = rem & 15;                 // % NDG
        int t      = threadIdx.x;

        // duplicated (w,w) pairs, row = 6 float2 = 48B
        __shared__ float2 swp[DG][6];
        if (t < DG) {
            int d = g * DG + t;
            #pragma unroll
            for (int k = 0; k < 5; k++) { float w = __ldg(W + d * 5 + k); swp[t][k] = make_float2(w, w); }
            float bb = __ldg(b + d); swp[t][5] = make_float2(bb, bb);
        }
        __syncthreads();

        unsigned wbase;
        { unsigned long long ga = __cvta_generic_to_shared(&swp[0][0]); wbase = (unsigned)ga; }

        int f4 = chunk * 256 + t;
        if (f4 >= ROW4) return;
        int p = f4 * 4;

        float4* po = out + ((long)(stream * 256 + g * DG) * ROW4 + f4);
        const float4 ZZ = make_float4(0.f, 0.f, 0.f, 0.f);

        if (stream == 0) {
            if (f4 < 3750) {                  // p < 15000
                float4 c = __ldg((const float4*)x250 + f4);
                u64t A01 = pk(c.x, c.y), A23 = pk(c.z, c.w);
                #pragma unroll 4
                for (int i = 0; i < DG; i++) {
                    unsigned wa = wbase + i * 48;
                    u64t W2 = lds64(wa + 16);
                    u64t BB = lds64(wa + 40);
                    Cvt o;
                    o.u.x = f2(W2, A01, BB);
                    o.u.y = f2(W2, A23, BB);
                    *po = o.f;  po += ROW4;
                }
            } else {
                #pragma unroll 8
                for (int i = 0; i < DG; i++) { *po = ZZ; po += ROW4; }
            }
        } else if (stream == 1) {
            if (f4 < 7500) {                  // p < 30000
                float v0 = ldx(x500, p - 1, L500);
                float4 c = __ldg((const float4*)x500 + f4);
                float v5 = ldx(x500, p + 4, L500);
                u64t Q0 = pk(v0, c.x), Q1 = pk(c.x, c.y), Q2 = pk(c.y, c.z),
                     Q3 = pk(c.z, c.w), Q4 = pk(c.w, v5);
                #pragma unroll 4
                for (int i = 0; i < DG; i++) {
                    unsigned wa = wbase + i * 48;
                    u64t W0 = lds64(wa + 0);
                    u64t W2 = lds64(wa + 16);
                    u64t W4 = lds64(wa + 32);
                    u64t BB = lds64(wa + 40);
                    Cvt o;
                    o.u.x = f2(W0, Q0, f2(W2, Q1, f2(W4, Q2, BB)));
                    o.u.y = f2(W0, Q2, f2(W2, Q3, f2(W4, Q4, BB)));
                    *po = o.f;  po += ROW4;
                }
            } else {
                #pragma unroll 8
                for (int i = 0; i < DG; i++) { *po = ZZ; po += ROW4; }
            }
        } else {
            float u0 = ldx(x1000, p - 2, L1000);
            float u1 = ldx(x1000, p - 1, L1000);
            float4 c = __ldg((const float4*)x1000 + f4);
            float u6 = ldx(x1000, p + 4, L1000);
            float u7 = ldx(x1000, p + 5, L1000);
            u64t P0 = pk(u0, u1),  P1 = pk(u1, c.x), P2 = pk(c.x, c.y),
                 P3 = pk(c.y, c.z), P4 = pk(c.z, c.w), P5 = pk(c.w, u6),
                 P6 = pk(u6, u7);
            #pragma unroll 4
            for (int i = 0; i < DG; i++) {
                unsigned wa = wbase + i * 48;
                u64t W0 = lds64(wa + 0);
                u64t W1 = lds64(wa + 8);
                u64t W2 = lds64(wa + 16);
                u64t W3 = lds64(wa + 24);
                u64t W4 = lds64(wa + 32);
                u64t BB = lds64(wa + 40);
                Cvt o;
                o.u.x = f2(W0, P0, f2(W1, P1, f2(W2, P2, f2(W3, P3, f2(W4, P4, BB)))));
                o.u.y = f2(W0, P2, f2(W1, P3, f2(W2, P4, f2(W3, P5, f2(W4, P6, BB)))));
                *po = o.f;  po += ROW4;
            }
        }
    } else {
        // S = [rows(60000), cols(60000)] as float
        int i = (blk - XBLOCKS) * 256 + threadIdx.x;
        if (i < S4TOT) {
            int e = i * 4;
            float4 o;
            float* pf = (float*)&o;
            if (e < L1000) {
                float r = (e < L250) ? 0.f : ((e < L250 + L500) ? 1.f : 2.f);
                o = make_float4(r, r, r, r);
            } else {
                int p = e - L1000;
                #pragma unroll
                for (int k = 0; k < 4; k++) {
                    int q = p + k;
                    float cc;
                    if (q < L250)             cc = (float)(q * 4);
                    else if (q < L250 + L500) cc = (float)((q - L250) * 2);
                    else                      cc = (float)(q - (L250 + L500));
                    pf[k] = cc;
                }
            }
            out[X4TOT + i] = o;
        }
    }
}

extern "C" void kernel_launch(void* const* d_in, const int* in_sizes, int n_in,
                              void* d_out, int out_size) {
    const float* x250  = (const float*)d_in[0];
    const float* x500  = (const float*)d_in[1];
    const float* x1000 = (const float*)d_in[2];
    const float* W     = (const float*)d_in[3];
    const float* b     = (const float*)d_in[4];
    float4* out = (float4*)d_out;

    embedder_kernel<<<XBLOCKS + SBLOCKS, 256>>>(x250, x500, x1000, W, b, out);
}

// round 11
// speedup vs baseline: 1.3113x; 1.0049x over previous
#include <cuda_runtime.h>

// Embedder: multirate zero-insert upsample -> conv1d(1->256, K=5, same) -> gather.
// Closed-form per-stream FIR taps. Output = X[3,256,60000] ++ S[2,60000] (~185 MB).
//
// R11 = R5 (best: d-reuse, smem weight broadcast, __stcs, DG=32/NDG=8)
//     + heavy-first block ordering: stream2 (5-tap) blocks launch FIRST,
//       stream0 (mostly zero-store) blocks LAST, so the final wave drains at
//       the LTS write cap instead of stretching the tail with compute.
// Evidence: 6 designs pinned at 28.6-30.6us = 185MB / ~6.5TB/s LTS cap.

#define L250   15000
#define L500   30000
#define L1000  60000
#define ROW4   15000                       // float4 per (stream,d) row
#define X4TOT  (768 * ROW4)                // 11,520,000 float4
#define S4TOT  30000
#define NCH    59                          // ceil(15000 / 256)
#define NDG    8                           // 8 groups of 32 d
#define DG     32
#define XBLOCKS (3 * NCH * NDG)            // 1416
#define SBLOCKS ((S4TOT + 255) / 256)      // 118

__device__ __forceinline__ float ldx(const float* __restrict__ x, int i, int l) {
    return (i >= 0 && i < l) ? __ldg(x + i) : 0.0f;
}

__global__ void __launch_bounds__(256)
embedder_kernel(const float* __restrict__ x250,
                const float* __restrict__ x500,
                const float* __restrict__ x1000,
                const float* __restrict__ W,   // [256,1,5]
                const float* __restrict__ b,   // [256]
                float4* __restrict__ out)
{
    int blk = blockIdx.x;

    if (blk < XBLOCKS) {
        int sblk   = blk / (NCH * NDG);
        int stream = 2 - sblk;                 // heavy-first: 2, then 1, then 0
        int rem    = blk - sblk * (NCH * NDG);
        int chunk  = rem >> 3;                 // / NDG
        int g      = rem & 7;                  // % NDG
        int t      = threadIdx.x;

        __shared__ float sw[DG][6];            // {w0,w1,w2,w3,w4,b} per d
        if (t < DG) {
            int d = g * DG + t;
            #pragma unroll
            for (int k = 0; k < 5; k++) sw[t][k] = __ldg(W + d * 5 + k);
            sw[t][5] = __ldg(b + d);
        }
        __syncthreads();

        int f4 = chunk * 256 + t;
        if (f4 >= ROW4) return;
        int p = f4 * 4;

        float4* po = out + ((long)(stream * 256 + g * DG) * ROW4 + f4);
        const float4 ZZ = make_float4(0.f, 0.f, 0.f, 0.f);

        if (stream == 0) {
            if (f4 < 3750) {                  // p < 15000
                float4 c = __ldg((const float4*)x250 + f4);
                #pragma unroll 4
                for (int i = 0; i < DG; i++) {
                    float2 cd = *(const float2*)&sw[i][2];   // w2, w3
                    float2 ef = *(const float2*)&sw[i][4];   // w4, b
                    float w2 = cd.x, bb = ef.y;
                    float4 o;
                    o.x = fmaf(w2, c.x, bb);
                    o.y = fmaf(w2, c.y, bb);
                    o.z = fmaf(w2, c.z, bb);
                    o.w = fmaf(w2, c.w, bb);
                    __stcs(po, o);  po += ROW4;
                }
            } else {
                #pragma unroll 8
                for (int i = 0; i < DG; i++) { __stcs(po, ZZ); po += ROW4; }
            }
        } else if (stream == 1) {
            if (f4 < 7500) {                  // p < 30000
                float v0 = ldx(x500, p - 1, L500);
                float4 c = __ldg((const float4*)x500 + f4);
                float v5 = ldx(x500, p + 4, L500);
                #pragma unroll 4
                for (int i = 0; i < DG; i++) {
                    float2 ab = *(const float2*)&sw[i][0];
                    float2 cd = *(const float2*)&sw[i][2];
                    float2 ef = *(const float2*)&sw[i][4];
                    float w0 = ab.x, w2 = cd.x, w4 = ef.x, bb = ef.y;
                    float4 o;
                    o.x = fmaf(w0, v0,  fmaf(w2, c.x, fmaf(w4, c.y, bb)));
                    o.y = fmaf(w0, c.x, fmaf(w2, c.y, fmaf(w4, c.z, bb)));
                    o.z = fmaf(w0, c.y, fmaf(w2, c.z, fmaf(w4, c.w, bb)));
                    o.w = fmaf(w0, c.z, fmaf(w2, c.w, fmaf(w4, v5,  bb)));
                    __stcs(po, o);  po += ROW4;
                }
            } else {
                #pragma unroll 8
                for (int i = 0; i < DG; i++) { __stcs(po, ZZ); po += ROW4; }
            }
        } else {
            float u0 = ldx(x1000, p - 2, L1000);
            float u1 = ldx(x1000, p - 1, L1000);
            float4 c = __ldg((const float4*)x1000 + f4);
            float u6 = ldx(x1000, p + 4, L1000);
            float u7 = ldx(x1000, p + 5, L1000);
            #pragma unroll 4
            for (int i = 0; i < DG; i++) {
                float2 ab = *(const float2*)&sw[i][0];
                float2 cd = *(const float2*)&sw[i][2];
                float2 ef = *(const float2*)&sw[i][4];
                float4 o;
                o.x = fmaf(ab.x, u0,  fmaf(ab.y, u1,  fmaf(cd.x, c.x, fmaf(cd.y, c.y, fmaf(ef.x, c.z, ef.y)))));
                o.y = fmaf(ab.x, u1,  fmaf(ab.y, c.x, fmaf(cd.x, c.y, fmaf(cd.y, c.z, fmaf(ef.x, c.w, ef.y)))));
                o.z = fmaf(ab.x, c.x, fmaf(ab.y, c.y, fmaf(cd.x, c.z, fmaf(cd.y, c.w, fmaf(ef.x, u6,  ef.y)))));
                o.w = fmaf(ab.x, c.y, fmaf(ab.y, c.z, fmaf(cd.x, c.w, fmaf(cd.y, u6,  fmaf(ef.x, u7,  ef.y)))));
                __stcs(po, o);  po += ROW4;
            }
        }
    } else {
        // S = [rows(60000), cols(60000)] as float
        int i = (blk - XBLOCKS) * 256 + threadIdx.x;
        if (i < S4TOT) {
            int e = i * 4;
            float4 o;
            float* pf = (float*)&o;
            if (e < L1000) {
                float r = (e < L250) ? 0.f : ((e < L250 + L500) ? 1.f : 2.f);
                o = make_float4(r, r, r, r);
            } else {
                int p = e - L1000;
                #pragma unroll
                for (int k = 0; k < 4; k++) {
                    int q = p + k;
                    float cc;
                    if (q < L250)             cc = (float)(q * 4);
                    else if (q < L250 + L500) cc = (float)((q - L250) * 2);
                    else                      cc = (float)(q - (L250 + L500));
                    pf[k] = cc;
                }
            }
            __stcs(out + X4TOT + i, o);
        }
    }
}

extern "C" void kernel_launch(void* const* d_in, const int* in_sizes, int n_in,
                              void* d_out, int out_size) {
    const float* x250  = (const float*)d_in[0];
    const float* x500  = (const float*)d_in[1];
    const float* x1000 = (const float*)d_in[2];
    const float* W     = (const float*)d_in[3];
    const float* b     = (const float*)d_in[4];
    float4* out = (float4*)d_out;

    embedder_kernel<<<XBLOCKS + SBLOCKS, 256>>>(x250, x500, x1000, W, b, out);
}

// round 12
// speedup vs baseline: 1.3811x; 1.0533x over previous
#include <cuda_runtime.h>

// Embedder: multirate zero-insert upsample -> conv1d(1->256, K=5, same) -> gather.
// Closed-form per-stream FIR taps. Output = X[3,256,60000] ++ S[2,60000] (~185 MB).
//
// FINAL (R12): Seven distinct designs (R4-R11) all pin at 28.6-30.6us kernel
// time regardless of instruction count, occupancy, store policy, or ordering.
// 185 MB / 28.6us = 6.4 TB/s = effective HBM write-path ceiling. The kernel is
// write-bandwidth terminal. This version = best-measured core (R5: d-reuse,
// smem weight broadcast LDS.64, __stcs, DG=32/NDG=8) + heavy-first stream
// ordering + store-only blocks (zero regions, S) draining in the final wave.

#define L250   15000
#define L500   30000
#define L1000  60000
#define ROW4   15000                       // float4 per (stream,d) row
#define X4TOT  (768 * ROW4)                // 11,520,000 float4
#define S4TOT  30000
#define NCH    59                          // ceil(15000 / 256)
#define NDG    8                           // 8 groups of 32 d
#define DG     32
#define XBLOCKS (3 * NCH * NDG)            // 1416
#define SBLOCKS ((S4TOT + 255) / 256)      // 118

__device__ __forceinline__ float ldx(const float* __restrict__ x, int i, int l) {
    return (i >= 0 && i < l) ? __ldg(x + i) : 0.0f;
}

__global__ void __launch_bounds__(256)
embedder_kernel(const float* __restrict__ x250,
                const float* __restrict__ x500,
                const float* __restrict__ x1000,
                const float* __restrict__ W,   // [256,1,5]
                const float* __restrict__ b,   // [256]
                float4* __restrict__ out)
{
    int blk = blockIdx.x;

    if (blk < XBLOCKS) {
        int sblk   = blk / (NCH * NDG);
        int stream = 2 - sblk;                 // heavy-first: 2, then 1, then 0
        int rem    = blk - sblk * (NCH * NDG);
        int chunk  = rem >> 3;                 // / NDG
        int g      = rem & 7;                  // % NDG
        int t      = threadIdx.x;

        __shared__ float sw[DG][6];            // {w0,w1,w2,w3,w4,b} per d
        if (t < DG) {
            int d = g * DG + t;
            #pragma unroll
            for (int k = 0; k < 5; k++) sw[t][k] = __ldg(W + d * 5 + k);
            sw[t][5] = __ldg(b + d);
        }
        __syncthreads();

        int f4 = chunk * 256 + t;
        if (f4 >= ROW4) return;
        int p = f4 * 4;

        float4* po = out + ((long)(stream * 256 + g * DG) * ROW4 + f4);
        const float4 ZZ = make_float4(0.f, 0.f, 0.f, 0.f);

        if (stream == 0) {
            if (f4 < 3750) {                  // p < 15000
                float4 c = __ldg((const float4*)x250 + f4);
                #pragma unroll 4
                for (int i = 0; i < DG; i++) {
                    float2 cd = *(const float2*)&sw[i][2];   // w2, w3
                    float2 ef = *(const float2*)&sw[i][4];   // w4, b
                    float w2 = cd.x, bb = ef.y;
                    float4 o;
                    o.x = fmaf(w2, c.x, bb);
                    o.y = fmaf(w2, c.y, bb);
                    o.z = fmaf(w2, c.z, bb);
                    o.w = fmaf(w2, c.w, bb);
                    __stcs(po, o);  po += ROW4;
                }
            } else {
                #pragma unroll 8
                for (int i = 0; i < DG; i++) { __stcs(po, ZZ); po += ROW4; }
            }
        } else if (stream == 1) {
            if (f4 < 7500) {                  // p < 30000
                float v0 = ldx(x500, p - 1, L500);
                float4 c = __ldg((const float4*)x500 + f4);
                float v5 = ldx(x500, p + 4, L500);
                #pragma unroll 4
                for (int i = 0; i < DG; i++) {
                    float2 ab = *(const float2*)&sw[i][0];
                    float2 cd = *(const float2*)&sw[i][2];
                    float2 ef = *(const float2*)&sw[i][4];
                    float w0 = ab.x, w2 = cd.x, w4 = ef.x, bb = ef.y;
                    float4 o;
                    o.x = fmaf(w0, v0,  fmaf(w2, c.x, fmaf(w4, c.y, bb)));
                    o.y = fmaf(w0, c.x, fmaf(w2, c.y, fmaf(w4, c.z, bb)));
                    o.z = fmaf(w0, c.y, fmaf(w2, c.z, fmaf(w4, c.w, bb)));
                    o.w = fmaf(w0, c.z, fmaf(w2, c.w, fmaf(w4, v5,  bb)));
                    __stcs(po, o);  po += ROW4;
                }
            } else {
                #pragma unroll 8
                for (int i = 0; i < DG; i++) { __stcs(po, ZZ); po += ROW4; }
            }
        } else {
            float u0 = ldx(x1000, p - 2, L1000);
            float u1 = ldx(x1000, p - 1, L1000);
            float4 c = __ldg((const float4*)x1000 + f4);
            float u6 = ldx(x1000, p + 4, L1000);
            float u7 = ldx(x1000, p + 5, L1000);
            #pragma unroll 4
            for (int i = 0; i < DG; i++) {
                float2 ab = *(const float2*)&sw[i][0];
                float2 cd = *(const float2*)&sw[i][2];
                float2 ef = *(const float2*)&sw[i][4];
                float4 o;
                o.x = fmaf(ab.x, u0,  fmaf(ab.y, u1,  fmaf(cd.x, c.x, fmaf(cd.y, c.y, fmaf(ef.x, c.z, ef.y)))));
                o.y = fmaf(ab.x, u1,  fmaf(ab.y, c.x, fmaf(cd.x, c.y, fmaf(cd.y, c.z, fmaf(ef.x, c.w, ef.y)))));
                o.z = fmaf(ab.x, c.x, fmaf(ab.y, c.y, fmaf(cd.x, c.z, fmaf(cd.y, c.w, fmaf(ef.x, u6,  ef.y)))));
                o.w = fmaf(ab.x, c.y, fmaf(ab.y, c.z, fmaf(cd.x, c.w, fmaf(cd.y, u6,  fmaf(ef.x, u7,  ef.y)))));
                __stcs(po, o);  po += ROW4;
            }
        }
    } else {
        // S = [rows(60000), cols(60000)] as float — store-only tail blocks
        int i = (blk - XBLOCKS) * 256 + threadIdx.x;
        if (i < S4TOT) {
            int e = i * 4;
            float4 o;
            float* pf = (float*)&o;
            if (e < L1000) {
                float r = (e < L250) ? 0.f : ((e < L250 + L500) ? 1.f : 2.f);
                o = make_float4(r, r, r, r);
            } else {
                int p = e - L1000;
                #pragma unroll
                for (int k = 0; k < 4; k++) {
                    int q = p + k;
                    float cc;
                    if (q < L250)             cc = (float)(q * 4);
                    else if (q < L250 + L500) cc = (float)((q - L250) * 2);
                    else                      cc = (float)(q - (L250 + L500));
                    pf[k] = cc;
                }
            }
            __stcs(out + X4TOT + i, o);
        }
    }
}

extern "C" void kernel_launch(void* const* d_in, const int* in_sizes, int n_in,
                              void* d_out, int out_size) {
    const float* x250  = (const float*)d_in[0];
    const float* x500  = (const float*)d_in[1];
    const float* x1000 = (const float*)d_in[2];
    const float* W     = (const float*)d_in[3];
    const float* b     = (const float*)d_in[4];
    float4* out = (float4*)d_out;

    embedder_kernel<<<XBLOCKS + SBLOCKS, 256>>>(x250, x500, x1000, W, b, out);
}